// round 14
// baseline (speedup 1.0000x reference)
#include <cuda_runtime.h>
#include <cstdint>

// ---------------------------------------------------------------------------
// Problem constants
// ---------------------------------------------------------------------------
#define NPOS    4096     // H*W
#define CTOT    64
#define NBATCH  2
#define NBH     16       // batch*heads
#define NSPLIT  4        // split-K factor (1024 keys per block, staged once)

// Raw-view semantics (faithful to the reference's .view):
//   Q/K/V[bh][row][d] = conv.flat[bh*32768 + row*8 + d]
//                     = conv[b][8h + (row>>9)][8*(row&511) + d]
// Q fp32 flat [b][c][n]. K fp16: g_kh[bh][key][dpair] (half2 lo = even d).
// V fp16 transposed: g_vh[bh][d][keypair] (half2 lo = even key).
__device__ float    g_q [NBATCH * CTOT * NPOS];
__device__ uint32_t g_kh[NBH * NPOS * 4];
__device__ uint32_t g_vh[NBH * 8 * 2048];

// Split-K partials
__device__ float g_po[NSPLIT * NBH * NPOS * 8];
__device__ float g_pl[NSPLIT * NBH * NPOS];

// ---------------------------------------------------------------------------
// Helpers
// ---------------------------------------------------------------------------
__device__ __forceinline__ uint32_t pack_h2(float hi, float lo) {
    uint32_t d;
    asm("cvt.rn.f16x2.f32 %0, %1, %2;" : "=r"(d) : "f"(hi), "f"(lo));
    return d;
}
__device__ __forceinline__ uint32_t ex2_h2(uint32_t s) {
    uint32_t d;
    asm("ex2.approx.f16x2 %0, %1;" : "=r"(d) : "r"(s));
    return d;
}
__device__ __forceinline__ uint32_t hadd2(uint32_t a, uint32_t b) {
    uint32_t d;
    asm("add.f16x2 %0, %1, %2;" : "=r"(d) : "r"(a), "r"(b));
    return d;
}
__device__ __forceinline__ float2 h2_to_f2(uint32_t h) {
    float lo, hi;
    asm("{ .reg .f16 a, b; mov.b32 {a, b}, %2; "
        "cvt.f32.f16 %0, a; cvt.f32.f16 %1, b; }"
        : "=f"(lo), "=f"(hi) : "r"(h));
    return make_float2(lo, hi);
}
__device__ __forceinline__ uint32_t smem_u32(const void* p) {
    uint32_t a;
    asm("{ .reg .u64 t; cvta.to.shared.u64 t, %1; cvt.u32.u64 %0, t; }"
        : "=r"(a) : "l"(p));
    return a;
}
__device__ __forceinline__ void cp16(uint32_t dst, const void* src) {
    asm volatile("cp.async.cg.shared.global [%0], [%1], 16;"
                 :: "r"(dst), "l"(src) : "memory");
}
#define CP_COMMIT() asm volatile("cp.async.commit_group;" ::: "memory")
#define CP_WAIT0()  asm volatile("cp.async.wait_group 0;" ::: "memory")

// fp16 m16n8k8 (S = Q K^T). lane = g*4+c.
__device__ __forceinline__ void mma_h_k8(
    float& d0, float& d1, float& d2, float& d3,
    uint32_t a0, uint32_t a1, uint32_t b0)
{
    asm volatile(
        "mma.sync.aligned.m16n8k8.row.col.f32.f16.f16.f32 "
        "{%0,%1,%2,%3}, {%4,%5}, {%6}, {%7,%8,%9,%10};"
        : "=f"(d0), "=f"(d1), "=f"(d2), "=f"(d3)
        : "r"(a0), "r"(a1), "r"(b0),
          "f"(0.f), "f"(0.f), "f"(0.f), "f"(0.f));
}

// fp16 m16n8k16 (PV).
__device__ __forceinline__ void mma_h_k16(
    float* d, uint32_t a0, uint32_t a1, uint32_t a2, uint32_t a3,
    uint32_t b0, uint32_t b1)
{
    asm volatile(
        "mma.sync.aligned.m16n8k16.row.col.f32.f16.f16.f32 "
        "{%0,%1,%2,%3}, {%4,%5,%6,%7}, {%8,%9}, {%0,%1,%2,%3};"
        : "+f"(d[0]), "+f"(d[1]), "+f"(d[2]), "+f"(d[3])
        : "r"(a0), "r"(a1), "r"(a2), "r"(a3), "r"(b0), "r"(b1));
}

// ---------------------------------------------------------------------------
// Kernel 1: fused QKV projection + fp16 repack (raw-view semantics).
// Unchanged from round 13 (14.1us measured).
// ---------------------------------------------------------------------------
__global__ __launch_bounds__(256) void proj_kernel(
    const float* __restrict__ x,
    const float* __restrict__ wq, const float* __restrict__ bq,
    const float* __restrict__ wk, const float* __restrict__ bk,
    const float* __restrict__ wv, const float* __restrict__ bv)
{
    __shared__ float xs[CTOT * 32];                 // 8KB
    __shared__ float wsq[32 * CTOT];                // 8KB
    __shared__ float wsk[32 * CTOT];                // 8KB
    __shared__ float wsv[32 * CTOT];                // 8KB
    __shared__ unsigned short vsm[32][34];          // 2.125KB

    const int b     = blockIdx.z;
    const int cbase = blockIdx.y * 32;
    const int p0    = blockIdx.x * 32;
    const int tid   = threadIdx.x;

    {
        const float4* xg = (const float4*)(x + b * (CTOT * NPOS));
        const float4* wq4 = (const float4*)(wq + cbase * CTOT);
        const float4* wk4 = (const float4*)(wk + cbase * CTOT);
        const float4* wv4 = (const float4*)(wv + cbase * CTOT);
        #pragma unroll
        for (int k = 0; k < 2; k++) {
            const int j = tid + k * 256;
            ((float4*)xs)[j]  = xg[(j >> 3) * 1024 + (p0 >> 2) + (j & 7)];
            ((float4*)wsq)[j] = wq4[j];
            ((float4*)wsk)[j] = wk4[j];
            ((float4*)wsv)[j] = wv4[j];
        }
    }
    __syncthreads();

    const int cp = tid >> 4;
    const int pg = tid & 15;
    const int l0 = 2 * cp, l1 = l0 + 1;
    const int c0 = cbase + l0, c1 = c0 + 1;

    float fq0[2], fq1[2], fk0[2], fk1[2], fv0[2], fv1[2];
    fq0[0] = fq0[1] = bq[c0];  fq1[0] = fq1[1] = bq[c1];
    fk0[0] = fk0[1] = bk[c0];  fk1[0] = fk1[1] = bk[c1];
    fv0[0] = fv0[1] = bv[c0];  fv1[0] = fv1[1] = bv[c1];

    #pragma unroll
    for (int cc = 0; cc < CTOT; cc += 4) {
        const float4 wq0 = *(const float4*)(wsq + l0 * CTOT + cc);
        const float4 wq1 = *(const float4*)(wsq + l1 * CTOT + cc);
        const float4 wk0 = *(const float4*)(wsk + l0 * CTOT + cc);
        const float4 wk1 = *(const float4*)(wsk + l1 * CTOT + cc);
        const float4 wv0 = *(const float4*)(wsv + l0 * CTOT + cc);
        const float4 wv1 = *(const float4*)(wsv + l1 * CTOT + cc);
        const float wq0a[4] = {wq0.x, wq0.y, wq0.z, wq0.w};
        const float wq1a[4] = {wq1.x, wq1.y, wq1.z, wq1.w};
        const float wk0a[4] = {wk0.x, wk0.y, wk0.z, wk0.w};
        const float wk1a[4] = {wk1.x, wk1.y, wk1.z, wk1.w};
        const float wv0a[4] = {wv0.x, wv0.y, wv0.z, wv0.w};
        const float wv1a[4] = {wv1.x, wv1.y, wv1.z, wv1.w};
        #pragma unroll
        for (int k = 0; k < 4; k++) {
            const float2 xv = *(const float2*)(xs + (cc + k) * 32 + 2 * pg);
            const float xa[2] = {xv.x, xv.y};
            #pragma unroll
            for (int i = 0; i < 2; i++) {
                fq0[i] = fmaf(wq0a[k], xa[i], fq0[i]);
                fq1[i] = fmaf(wq1a[k], xa[i], fq1[i]);
                fk0[i] = fmaf(wk0a[k], xa[i], fk0[i]);
                fk1[i] = fmaf(wk1a[k], xa[i], fk1[i]);
                fv0[i] = fmaf(wv0a[k], xa[i], fv0[i]);
                fv1[i] = fmaf(wv1a[k], xa[i], fv1[i]);
            }
        }
    }

    const int p = p0 + 2 * pg;
    *(float2*)&g_q[b * (CTOT * NPOS) + c0 * NPOS + p] = make_float2(fq0[0], fq0[1]);
    *(float2*)&g_q[b * (CTOT * NPOS) + c1 * NPOS + p] = make_float2(fq1[0], fq1[1]);

    {
        const int h   = c0 >> 3;
        const int bh  = b * 8 + h;
        const int cw0 = c0 & 7, cw1 = cw0 + 1;
        const int kb  = (p >> 3) & 511;
        const int dp  = (p >> 1) & 3;
        g_kh[(bh * NPOS + 512 * cw0 + kb) * 4 + dp] = pack_h2(fk0[1], fk0[0]);
        g_kh[(bh * NPOS + 512 * cw1 + kb) * 4 + dp] = pack_h2(fk1[1], fk1[0]);
    }

    {
        const int pl = 2 * pg;
        *(uint32_t*)&vsm[l0][pl] = pack_h2(fv0[1], fv0[0]);
        *(uint32_t*)&vsm[l1][pl] = pack_h2(fv1[1], fv1[0]);
    }
    __syncthreads();

    {
        const int lc = tid & 31;
        const int d  = tid >> 5;
        const int cg = cbase + lc;
        const int h  = cg >> 3;
        const int cw = cg & 7;
        const int ob = ((b * 8 + h) * 8 + d) * 2048 + cw * 256 + (p0 >> 4);
        #pragma unroll
        for (int kl = 0; kl < 2; kl++) {
            const uint32_t lo = vsm[lc][16 * kl + d];
            const uint32_t hi = vsm[lc][16 * kl + 8 + d];
            g_vh[ob + kl] = (hi << 16) | lo;
        }
    }
}

// ---------------------------------------------------------------------------
// Kernel 2: split-K fp16 flash attention (no-max softmax). NSPLIT=4.
// Single-shot staging; 64 pure-compute u-iterations. Row sums now on the
// fma pipe (add.f16x2 pairs, fp32 flush every 8 u) instead of the ones-mma
// -> tensor demand per u drops from 2k8+2k16 to 2k8+1k16.
// ---------------------------------------------------------------------------
struct __align__(16) KVBuf {
    uint32_t ks[1024 * 4];    // K: word = key*4 + dpair             (16384B)
    uint32_t vs[8 * 516];     // V: word = d*516 + keypair (pad 4)   (16512B)
};

__global__ __launch_bounds__(128, 6) void attn_mma_kernel(void)
{
    __shared__ KVBuf buf;     // 32.9KB -> 6 blocks/SM

    const int tid  = threadIdx.x;
    const int w    = tid >> 5;
    const int lane = tid & 31;
    const int g    = lane >> 2;
    const int c    = lane & 3;
    const int bh   = blockIdx.y;
    const int sp   = blockIdx.z;
    const int q0   = blockIdx.x * 64;
    const int base = bh * (8 * NPOS);

    // ---- stage 1024 keys of K and V with one cp.async batch
    {
        const uint32_t ks_s = smem_u32(buf.ks);
        const uint32_t vs_s = smem_u32(buf.vs);
        const uint4* kg = (const uint4*)g_kh + bh * 4096 + sp * 1024;
        const uint4* vg = (const uint4*)g_vh + bh * 4096 + sp * 128;
        #pragma unroll
        for (int i = 0; i < 8; i++) {
            const int idx = tid + i * 128;
            cp16(ks_s + (uint32_t)idx * 16u, kg + idx);
        }
        #pragma unroll
        for (int i = 0; i < 8; i++) {
            const int idx = tid + i * 128;
            const int d   = idx >> 7;
            const int col = idx & 127;
            cp16(vs_s + (uint32_t)(d * 2064 + col * 16), vg + d * 512 + col);
        }
        CP_COMMIT();
    }

    // Q fragment fp16 (scaled by log2(e)/sqrt(8)); raw-view read.
    const float SC = 0.51012921003633f;
    const int qr0 = q0 + 16 * w + g;
    const float2 ql = *(const float2*)&g_q[base + qr0 * 8 + 2 * c];
    const float2 qh = *(const float2*)&g_q[base + (qr0 + 8) * 8 + 2 * c];
    const uint32_t qa0 = pack_h2(ql.y * SC, ql.x * SC);
    const uint32_t qa1 = pack_h2(qh.y * SC, qh.x * SC);

    float o0[4] = {0.f, 0.f, 0.f, 0.f};
    float o1[4] = {0.f, 0.f, 0.f, 0.f};
    float lA = 0.f, lB = 0.f;      // fp32 row-sum partials (rows g, g+8)

    CP_WAIT0();
    __syncthreads();   // the ONLY barrier in the kernel

    const uint32_t* ksb = buf.ks;
    const uint32_t* vsb = buf.vs;

    #pragma unroll 2
    for (int ug = 0; ug < 8; ug++) {
        uint32_t h2a = 0u, h2b = 0u;   // fp16x2 partials for this 8-u group
        #pragma unroll
        for (int uu = 0; uu < 8; uu++) {
            const int u = ug * 8 + uu;
            // keys 16u .. 16u+7
            float s0, s1, s2, s3;
            mma_h_k8(s0, s1, s2, s3, qa0, qa1, ksb[(16 * u + g) * 4 + c]);
            const uint32_t pa0 = ex2_h2(pack_h2(s1, s0));
            const uint32_t pa1 = ex2_h2(pack_h2(s3, s2));
            // keys 16u+8 .. 16u+15
            float t0, t1, t2, t3;
            mma_h_k8(t0, t1, t2, t3, qa0, qa1, ksb[(16 * u + 8 + g) * 4 + c]);
            const uint32_t pa2 = ex2_h2(pack_h2(t1, t0));
            const uint32_t pa3 = ex2_h2(pack_h2(t3, t2));

            // row sums on the fma pipe (was a k16 ones-mma)
            h2a = hadd2(h2a, hadd2(pa0, pa2));   // row g
            h2b = hadd2(h2b, hadd2(pa1, pa3));   // row g+8

            const uint32_t vb0 = vsb[g * 516 + 8 * u + c];
            const uint32_t vb1 = vsb[g * 516 + 8 * u + c + 4];
            if (u & 1) mma_h_k16(o1, pa0, pa1, pa2, pa3, vb0, vb1);
            else       mma_h_k16(o0, pa0, pa1, pa2, pa3, vb0, vb1);
        }
        // flush group partials to fp32 (max ~6.7K, well inside fp16 range)
        const float2 fa = h2_to_f2(h2a);
        const float2 fb = h2_to_f2(h2b);
        lA += fa.x + fa.y;
        lB += fb.x + fb.y;
    }

    #pragma unroll
    for (int i = 0; i < 4; i++) o0[i] += o1[i];

    // quad reduction over lanes sharing g (c = lane bits 0-1)
    lA += __shfl_xor_sync(0xffffffffu, lA, 1);
    lA += __shfl_xor_sync(0xffffffffu, lA, 2);
    lB += __shfl_xor_sync(0xffffffffu, lB, 1);
    lB += __shfl_xor_sync(0xffffffffu, lB, 2);

    // partials
    const int pbase = (sp * NBH + bh) * NPOS;
    const int n0 = qr0, n1 = qr0 + 8;
    const int d0 = 2 * c;
    *(float2*)&g_po[(pbase + n0) * 8 + d0] = make_float2(o0[0], o0[1]);
    *(float2*)&g_po[(pbase + n1) * 8 + d0] = make_float2(o0[2], o0[3]);
    if (c == 0) {
        g_pl[pbase + n0] = lA;
        g_pl[pbase + n1] = lB;
    }
}

// ---------------------------------------------------------------------------
// Kernel 3: combine 4 split-K partials + fused epilogue (512 blocks x 128)
// ---------------------------------------------------------------------------
__global__ __launch_bounds__(128) void combine_kernel(
    const float* __restrict__ x,
    const float* __restrict__ gamma,
    float* __restrict__ out)
{
    const int i  = blockIdx.x * 128 + threadIdx.x;
    const int bh = i >> 12;
    const int n  = i & 4095;

    float od[8] = {0.f,0.f,0.f,0.f,0.f,0.f,0.f,0.f};
    float l = 0.f;
    #pragma unroll
    for (int sp = 0; sp < NSPLIT; sp++) {
        const int pbase = (sp * NBH + bh) * NPOS;
        const float4* pa = (const float4*)&g_po[(pbase + n) * 8];
        const float4 a0 = pa[0], a1 = pa[1];
        od[0] += a0.x; od[1] += a0.y; od[2] += a0.z; od[3] += a0.w;
        od[4] += a1.x; od[5] += a1.y; od[6] += a1.z; od[7] += a1.w;
        l += g_pl[pbase + n];
    }

    const float inv = 1.0f / l;
    const float gm  = gamma[0];
    const int base  = bh * (8 * NPOS);
    #pragma unroll
    for (int d = 0; d < 8; d++) {
        const int idx = base + d * NPOS + n;
        out[idx] = fmaf(gm, od[d] * inv, x[idx]);
    }
}

// ---------------------------------------------------------------------------
extern "C" void kernel_launch(void* const* d_in, const int* in_sizes, int n_in,
                              void* d_out, int out_size)
{
    const float* x     = (const float*)d_in[0];
    const float* wq    = (const float*)d_in[1];
    const float* bq    = (const float*)d_in[2];
    const float* wk    = (const float*)d_in[3];
    const float* bk    = (const float*)d_in[4];
    const float* wv    = (const float*)d_in[5];
    const float* bv    = (const float*)d_in[6];
    const float* gamma = (const float*)d_in[7];
    float* out = (float*)d_out;

    proj_kernel<<<dim3(NPOS / 32, 2, NBATCH), 256>>>(x, wq, bq, wk, bk, wv, bv);
    attn_mma_kernel<<<dim3(NPOS / 64, NBH, NSPLIT), 128>>>();
    combine_kernel<<<dim3(NBH * NPOS / 128), 128>>>(x, gamma, out);
}

// round 15
// speedup vs baseline: 1.0576x; 1.0576x over previous
#include <cuda_runtime.h>
#include <cstdint>

// ---------------------------------------------------------------------------
// Problem constants
// ---------------------------------------------------------------------------
#define NPOS    4096     // H*W
#define CTOT    64
#define NBATCH  2
#define NBH     16       // batch*heads
#define NSPLIT  4        // split-K factor (1024 keys per block, staged once)

// Raw-view semantics (faithful to the reference's .view):
//   Q/K/V[bh][row][d] = conv.flat[bh*32768 + row*8 + d]
//                     = conv[b][8h + (row>>9)][8*(row&511) + d]
// Q fp32 flat [b][c][n]. K fp16: g_kh[bh][key][dpair] (half2 lo = even d).
// V fp16 transposed: g_vh[bh][d][keypair] (half2 lo = even key).
__device__ float    g_q [NBATCH * CTOT * NPOS];
__device__ uint32_t g_kh[NBH * NPOS * 4];
__device__ uint32_t g_vh[NBH * 8 * 2048];

// Split-K partials
__device__ float g_po[NSPLIT * NBH * NPOS * 8];
__device__ float g_pl[NSPLIT * NBH * NPOS];

// ---------------------------------------------------------------------------
// Helpers
// ---------------------------------------------------------------------------
__device__ __forceinline__ uint32_t pack_h2(float hi, float lo) {
    uint32_t d;
    asm("cvt.rn.f16x2.f32 %0, %1, %2;" : "=r"(d) : "f"(hi), "f"(lo));
    return d;
}
__device__ __forceinline__ uint32_t ex2_h2(uint32_t s) {
    uint32_t d;
    asm("ex2.approx.f16x2 %0, %1;" : "=r"(d) : "r"(s));
    return d;
}
__device__ __forceinline__ uint32_t smem_u32(const void* p) {
    uint32_t a;
    asm("{ .reg .u64 t; cvta.to.shared.u64 t, %1; cvt.u32.u64 %0, t; }"
        : "=r"(a) : "l"(p));
    return a;
}
__device__ __forceinline__ void cp16(uint32_t dst, const void* src) {
    asm volatile("cp.async.cg.shared.global [%0], [%1], 16;"
                 :: "r"(dst), "l"(src) : "memory");
}
#define CP_COMMIT() asm volatile("cp.async.commit_group;" ::: "memory")
#define CP_WAIT0()  asm volatile("cp.async.wait_group 0;" ::: "memory")

// fp16 m16n8k8 (S = Q K^T). lane = g*4+c.
__device__ __forceinline__ void mma_h_k8(
    float& d0, float& d1, float& d2, float& d3,
    uint32_t a0, uint32_t a1, uint32_t b0)
{
    asm volatile(
        "mma.sync.aligned.m16n8k8.row.col.f32.f16.f16.f32 "
        "{%0,%1,%2,%3}, {%4,%5}, {%6}, {%7,%8,%9,%10};"
        : "=f"(d0), "=f"(d1), "=f"(d2), "=f"(d3)
        : "r"(a0), "r"(a1), "r"(b0),
          "f"(0.f), "f"(0.f), "f"(0.f), "f"(0.f));
}

// fp16 m16n8k16 (PV and row-sum).
__device__ __forceinline__ void mma_h_k16(
    float* d, uint32_t a0, uint32_t a1, uint32_t a2, uint32_t a3,
    uint32_t b0, uint32_t b1)
{
    asm volatile(
        "mma.sync.aligned.m16n8k16.row.col.f32.f16.f16.f32 "
        "{%0,%1,%2,%3}, {%4,%5,%6,%7}, {%8,%9}, {%0,%1,%2,%3};"
        : "+f"(d[0]), "+f"(d[1]), "+f"(d[2]), "+f"(d[3])
        : "r"(a0), "r"(a1), "r"(a2), "r"(a3), "r"(b0), "r"(b1));
}

// ---------------------------------------------------------------------------
// Kernel 1: fused QKV projection + fp16 repack (raw-view semantics).
// Unchanged from round 13 (14.1us measured).
// ---------------------------------------------------------------------------
__global__ __launch_bounds__(256) void proj_kernel(
    const float* __restrict__ x,
    const float* __restrict__ wq, const float* __restrict__ bq,
    const float* __restrict__ wk, const float* __restrict__ bk,
    const float* __restrict__ wv, const float* __restrict__ bv)
{
    __shared__ float xs[CTOT * 32];                 // 8KB
    __shared__ float wsq[32 * CTOT];                // 8KB
    __shared__ float wsk[32 * CTOT];                // 8KB
    __shared__ float wsv[32 * CTOT];                // 8KB
    __shared__ unsigned short vsm[32][34];          // 2.125KB

    const int b     = blockIdx.z;
    const int cbase = blockIdx.y * 32;
    const int p0    = blockIdx.x * 32;
    const int tid   = threadIdx.x;

    {
        const float4* xg = (const float4*)(x + b * (CTOT * NPOS));
        const float4* wq4 = (const float4*)(wq + cbase * CTOT);
        const float4* wk4 = (const float4*)(wk + cbase * CTOT);
        const float4* wv4 = (const float4*)(wv + cbase * CTOT);
        #pragma unroll
        for (int k = 0; k < 2; k++) {
            const int j = tid + k * 256;
            ((float4*)xs)[j]  = xg[(j >> 3) * 1024 + (p0 >> 2) + (j & 7)];
            ((float4*)wsq)[j] = wq4[j];
            ((float4*)wsk)[j] = wk4[j];
            ((float4*)wsv)[j] = wv4[j];
        }
    }
    __syncthreads();

    const int cp = tid >> 4;
    const int pg = tid & 15;
    const int l0 = 2 * cp, l1 = l0 + 1;
    const int c0 = cbase + l0, c1 = c0 + 1;

    float fq0[2], fq1[2], fk0[2], fk1[2], fv0[2], fv1[2];
    fq0[0] = fq0[1] = bq[c0];  fq1[0] = fq1[1] = bq[c1];
    fk0[0] = fk0[1] = bk[c0];  fk1[0] = fk1[1] = bk[c1];
    fv0[0] = fv0[1] = bv[c0];  fv1[0] = fv1[1] = bv[c1];

    #pragma unroll
    for (int cc = 0; cc < CTOT; cc += 4) {
        const float4 wq0 = *(const float4*)(wsq + l0 * CTOT + cc);
        const float4 wq1 = *(const float4*)(wsq + l1 * CTOT + cc);
        const float4 wk0 = *(const float4*)(wsk + l0 * CTOT + cc);
        const float4 wk1 = *(const float4*)(wsk + l1 * CTOT + cc);
        const float4 wv0 = *(const float4*)(wsv + l0 * CTOT + cc);
        const float4 wv1 = *(const float4*)(wsv + l1 * CTOT + cc);
        const float wq0a[4] = {wq0.x, wq0.y, wq0.z, wq0.w};
        const float wq1a[4] = {wq1.x, wq1.y, wq1.z, wq1.w};
        const float wk0a[4] = {wk0.x, wk0.y, wk0.z, wk0.w};
        const float wk1a[4] = {wk1.x, wk1.y, wk1.z, wk1.w};
        const float wv0a[4] = {wv0.x, wv0.y, wv0.z, wv0.w};
        const float wv1a[4] = {wv1.x, wv1.y, wv1.z, wv1.w};
        #pragma unroll
        for (int k = 0; k < 4; k++) {
            const float2 xv = *(const float2*)(xs + (cc + k) * 32 + 2 * pg);
            const float xa[2] = {xv.x, xv.y};
            #pragma unroll
            for (int i = 0; i < 2; i++) {
                fq0[i] = fmaf(wq0a[k], xa[i], fq0[i]);
                fq1[i] = fmaf(wq1a[k], xa[i], fq1[i]);
                fk0[i] = fmaf(wk0a[k], xa[i], fk0[i]);
                fk1[i] = fmaf(wk1a[k], xa[i], fk1[i]);
                fv0[i] = fmaf(wv0a[k], xa[i], fv0[i]);
                fv1[i] = fmaf(wv1a[k], xa[i], fv1[i]);
            }
        }
    }

    const int p = p0 + 2 * pg;
    *(float2*)&g_q[b * (CTOT * NPOS) + c0 * NPOS + p] = make_float2(fq0[0], fq0[1]);
    *(float2*)&g_q[b * (CTOT * NPOS) + c1 * NPOS + p] = make_float2(fq1[0], fq1[1]);

    {
        const int h   = c0 >> 3;
        const int bh  = b * 8 + h;
        const int cw0 = c0 & 7, cw1 = cw0 + 1;
        const int kb  = (p >> 3) & 511;
        const int dp  = (p >> 1) & 3;
        g_kh[(bh * NPOS + 512 * cw0 + kb) * 4 + dp] = pack_h2(fk0[1], fk0[0]);
        g_kh[(bh * NPOS + 512 * cw1 + kb) * 4 + dp] = pack_h2(fk1[1], fk1[0]);
    }

    {
        const int pl = 2 * pg;
        *(uint32_t*)&vsm[l0][pl] = pack_h2(fv0[1], fv0[0]);
        *(uint32_t*)&vsm[l1][pl] = pack_h2(fv1[1], fv1[0]);
    }
    __syncthreads();

    {
        const int lc = tid & 31;
        const int d  = tid >> 5;
        const int cg = cbase + lc;
        const int h  = cg >> 3;
        const int cw = cg & 7;
        const int ob = ((b * 8 + h) * 8 + d) * 2048 + cw * 256 + (p0 >> 4);
        #pragma unroll
        for (int kl = 0; kl < 2; kl++) {
            const uint32_t lo = vsm[lc][16 * kl + d];
            const uint32_t hi = vsm[lc][16 * kl + 8 + d];
            g_vh[ob + kl] = (hi << 16) | lo;
        }
    }
}

// ---------------------------------------------------------------------------
// Kernel 2: split-K fp16 flash attention (no-max softmax). NSPLIT=4.
// Round-13 structure (single-shot staging, ones-mma row sums) with the one
// change: FOUR-way accumulator split (o[4], la[4], selected by u&3) to cut
// the per-accumulator mma RAW chain from 32 links to 16.
// ---------------------------------------------------------------------------
struct __align__(16) KVBuf {
    uint32_t ks[1024 * 4];    // K: word = key*4 + dpair             (16384B)
    uint32_t vs[8 * 516];     // V: word = d*516 + keypair (pad 4)   (16512B)
};

__global__ __launch_bounds__(128, 6) void attn_mma_kernel(void)
{
    __shared__ KVBuf buf;     // 32.9KB -> 6 blocks/SM

    const int tid  = threadIdx.x;
    const int w    = tid >> 5;
    const int lane = tid & 31;
    const int g    = lane >> 2;
    const int c    = lane & 3;
    const int bh   = blockIdx.y;
    const int sp   = blockIdx.z;
    const int q0   = blockIdx.x * 64;
    const int base = bh * (8 * NPOS);

    // ---- stage 1024 keys of K and V with one cp.async batch
    {
        const uint32_t ks_s = smem_u32(buf.ks);
        const uint32_t vs_s = smem_u32(buf.vs);
        const uint4* kg = (const uint4*)g_kh + bh * 4096 + sp * 1024;
        const uint4* vg = (const uint4*)g_vh + bh * 4096 + sp * 128;
        #pragma unroll
        for (int i = 0; i < 8; i++) {
            const int idx = tid + i * 128;
            cp16(ks_s + (uint32_t)idx * 16u, kg + idx);
        }
        #pragma unroll
        for (int i = 0; i < 8; i++) {
            const int idx = tid + i * 128;
            const int d   = idx >> 7;
            const int col = idx & 127;
            cp16(vs_s + (uint32_t)(d * 2064 + col * 16), vg + d * 512 + col);
        }
        CP_COMMIT();
    }

    // Q fragment fp16 (scaled by log2(e)/sqrt(8)); raw-view read.
    const float SC = 0.51012921003633f;
    const int qr0 = q0 + 16 * w + g;
    const float2 ql = *(const float2*)&g_q[base + qr0 * 8 + 2 * c];
    const float2 qh = *(const float2*)&g_q[base + (qr0 + 8) * 8 + 2 * c];
    const uint32_t qa0 = pack_h2(ql.y * SC, ql.x * SC);
    const uint32_t qa1 = pack_h2(qh.y * SC, qh.x * SC);

    float o[4][4]  = {{0.f,0.f,0.f,0.f},{0.f,0.f,0.f,0.f},
                      {0.f,0.f,0.f,0.f},{0.f,0.f,0.f,0.f}};
    float la[4][4] = {{0.f,0.f,0.f,0.f},{0.f,0.f,0.f,0.f},
                      {0.f,0.f,0.f,0.f},{0.f,0.f,0.f,0.f}};
    const uint32_t ONE2 = 0x3C003C00u;   // half2(1, 1)

    CP_WAIT0();
    __syncthreads();   // the ONLY barrier in the kernel

    const uint32_t* ksb = buf.ks;
    const uint32_t* vsb = buf.vs;

    #pragma unroll 16
    for (int u = 0; u < 64; u++) {
        // keys 16u .. 16u+7
        float s0, s1, s2, s3;
        mma_h_k8(s0, s1, s2, s3, qa0, qa1, ksb[(16 * u + g) * 4 + c]);
        const uint32_t pa0 = ex2_h2(pack_h2(s1, s0));
        const uint32_t pa1 = ex2_h2(pack_h2(s3, s2));
        // keys 16u+8 .. 16u+15
        float t0, t1, t2, t3;
        mma_h_k8(t0, t1, t2, t3, qa0, qa1, ksb[(16 * u + 8 + g) * 4 + c]);
        const uint32_t pa2 = ex2_h2(pack_h2(t1, t0));
        const uint32_t pa3 = ex2_h2(pack_h2(t3, t2));

        const uint32_t vb0 = vsb[g * 516 + 8 * u + c];
        const uint32_t vb1 = vsb[g * 516 + 8 * u + c + 4];

        mma_h_k16(la[u & 3], pa0, pa1, pa2, pa3, ONE2, ONE2);
        mma_h_k16(o[u & 3],  pa0, pa1, pa2, pa3, vb0, vb1);
    }

    #pragma unroll
    for (int i = 0; i < 4; i++) {
        o[0][i]  += o[1][i]  + o[2][i]  + o[3][i];
        la[0][i] += la[1][i] + la[2][i] + la[3][i];
    }

    // partials
    const int pbase = (sp * NBH + bh) * NPOS;
    const int n0 = qr0, n1 = qr0 + 8;
    const int d0 = 2 * c;
    *(float2*)&g_po[(pbase + n0) * 8 + d0] = make_float2(o[0][0], o[0][1]);
    *(float2*)&g_po[(pbase + n1) * 8 + d0] = make_float2(o[0][2], o[0][3]);
    if (c == 0) {
        g_pl[pbase + n0] = la[0][0];
        g_pl[pbase + n1] = la[0][2];
    }
}

// ---------------------------------------------------------------------------
// Kernel 3: combine 4 split-K partials + fused epilogue (512 blocks x 128)
// ---------------------------------------------------------------------------
__global__ __launch_bounds__(128) void combine_kernel(
    const float* __restrict__ x,
    const float* __restrict__ gamma,
    float* __restrict__ out)
{
    const int i  = blockIdx.x * 128 + threadIdx.x;
    const int bh = i >> 12;
    const int n  = i & 4095;

    float od[8] = {0.f,0.f,0.f,0.f,0.f,0.f,0.f,0.f};
    float l = 0.f;
    #pragma unroll
    for (int sp = 0; sp < NSPLIT; sp++) {
        const int pbase = (sp * NBH + bh) * NPOS;
        const float4* pa = (const float4*)&g_po[(pbase + n) * 8];
        const float4 a0 = pa[0], a1 = pa[1];
        od[0] += a0.x; od[1] += a0.y; od[2] += a0.z; od[3] += a0.w;
        od[4] += a1.x; od[5] += a1.y; od[6] += a1.z; od[7] += a1.w;
        l += g_pl[pbase + n];
    }

    const float inv = 1.0f / l;
    const float gm  = gamma[0];
    const int base  = bh * (8 * NPOS);
    #pragma unroll
    for (int d = 0; d < 8; d++) {
        const int idx = base + d * NPOS + n;
        out[idx] = fmaf(gm, od[d] * inv, x[idx]);
    }
}

// ---------------------------------------------------------------------------
extern "C" void kernel_launch(void* const* d_in, const int* in_sizes, int n_in,
                              void* d_out, int out_size)
{
    const float* x     = (const float*)d_in[0];
    const float* wq    = (const float*)d_in[1];
    const float* bq    = (const float*)d_in[2];
    const float* wk    = (const float*)d_in[3];
    const float* bk    = (const float*)d_in[4];
    const float* wv    = (const float*)d_in[5];
    const float* bv    = (const float*)d_in[6];
    const float* gamma = (const float*)d_in[7];
    float* out = (float*)d_out;

    proj_kernel<<<dim3(NPOS / 32, 2, NBATCH), 256>>>(x, wq, bq, wk, bk, wv, bv);
    attn_mma_kernel<<<dim3(NPOS / 64, NBH, NSPLIT), 128>>>();
    combine_kernel<<<dim3(NBH * NPOS / 128), 128>>>(x, gamma, out);
}

// round 16
// speedup vs baseline: 1.1776x; 1.1135x over previous
#include <cuda_runtime.h>
#include <cstdint>

// ---------------------------------------------------------------------------
// Problem constants
// ---------------------------------------------------------------------------
#define NPOS    4096     // H*W
#define CTOT    64
#define NBATCH  2
#define NBH     16       // batch*heads
#define NSPLIT  4        // split-K factor (1024 keys per block, staged once)

// Raw-view semantics (faithful to the reference's .view):
//   Q/K/V[bh][row][d] = conv.flat[bh*32768 + row*8 + d]
// Q fp32 flat [b][c][n]. K fp16: g_kh[bh][key][dpair] (half2 lo = even d).
// V fp16 transposed: g_vh[bh][d][keypair] (half2 lo = even key).
__device__ float    g_q [NBATCH * CTOT * NPOS];
__device__ uint32_t g_kh[NBH * NPOS * 4];
__device__ uint32_t g_vh[NBH * 8 * 2048];

// Split-K partials
__device__ float g_po[NSPLIT * NBH * NPOS * 8];
__device__ float g_pl[NSPLIT * NBH * NPOS];

// ---------------------------------------------------------------------------
// Helpers
// ---------------------------------------------------------------------------
__device__ __forceinline__ uint32_t pack_h2(float hi, float lo) {
    uint32_t d;
    asm("cvt.rn.f16x2.f32 %0, %1, %2;" : "=r"(d) : "f"(hi), "f"(lo));
    return d;
}
__device__ __forceinline__ uint32_t ex2_h2(uint32_t s) {
    uint32_t d;
    asm("ex2.approx.f16x2 %0, %1;" : "=r"(d) : "r"(s));
    return d;
}
// 2^s for f16x2 WITHOUT MUFU: exact exponent via fp16 magic-add bit trick,
// cubic polynomial for the fraction. Valid for s in [-14, ~16) (clamped low;
// high side bounded by data since ex2 path doesn't overflow either).
__device__ __forceinline__ uint32_t ex2_h2_poly(uint32_t s) {
    uint32_t sc, t, nv, f, q;
    asm("max.f16x2 %0, %1, %2;" : "=r"(sc) : "r"(s), "r"(0xCB00CB00u));   // clamp >= -14
    asm("add.rn.f16x2 %0, %1, %2;" : "=r"(t) : "r"(sc), "r"(0x66006600u)); // +1536: t=1536+rn(s)
    asm("add.rn.f16x2 %0, %1, %2;" : "=r"(nv) : "r"(t), "r"(0xE600E600u)); // -1536: n
    asm("sub.rn.f16x2 %0, %1, %2;" : "=r"(f) : "r"(sc), "r"(nv));          // f = s-n, |f|<=0.5
    const uint32_t e2n = (t - 0x65F165F1u) << 10;    // per-half (n+15)<<10 = bits of 2^n
    asm("fma.rn.f16x2 %0, %1, %2, %3;" : "=r"(q) : "r"(f), "r"(0x2B662B66u), "r"(0x33AF33AFu));
    asm("fma.rn.f16x2 %0, %1, %2, %3;" : "=r"(q) : "r"(f), "r"(q), "r"(0x398C398Cu));
    asm("fma.rn.f16x2 %0, %1, %2, %3;" : "=r"(q) : "r"(f), "r"(q), "r"(0x3C003C00u));
    uint32_t p;
    asm("mul.rn.f16x2 %0, %1, %2;" : "=r"(p) : "r"(q), "r"(e2n));
    return p;
}
__device__ __forceinline__ uint32_t smem_u32(const void* p) {
    uint32_t a;
    asm("{ .reg .u64 t; cvta.to.shared.u64 t, %1; cvt.u32.u64 %0, t; }"
        : "=r"(a) : "l"(p));
    return a;
}
__device__ __forceinline__ void cp16(uint32_t dst, const void* src) {
    asm volatile("cp.async.cg.shared.global [%0], [%1], 16;"
                 :: "r"(dst), "l"(src) : "memory");
}
#define CP_COMMIT() asm volatile("cp.async.commit_group;" ::: "memory")
#define CP_WAIT0()  asm volatile("cp.async.wait_group 0;" ::: "memory")

// fp16 m16n8k8 (S = Q K^T). lane = g*4+c.
__device__ __forceinline__ void mma_h_k8(
    float& d0, float& d1, float& d2, float& d3,
    uint32_t a0, uint32_t a1, uint32_t b0)
{
    asm volatile(
        "mma.sync.aligned.m16n8k8.row.col.f32.f16.f16.f32 "
        "{%0,%1,%2,%3}, {%4,%5}, {%6}, {%7,%8,%9,%10};"
        : "=f"(d0), "=f"(d1), "=f"(d2), "=f"(d3)
        : "r"(a0), "r"(a1), "r"(b0),
          "f"(0.f), "f"(0.f), "f"(0.f), "f"(0.f));
}

// fp16 m16n8k16 (PV and row-sum).
__device__ __forceinline__ void mma_h_k16(
    float* d, uint32_t a0, uint32_t a1, uint32_t a2, uint32_t a3,
    uint32_t b0, uint32_t b1)
{
    asm volatile(
        "mma.sync.aligned.m16n8k16.row.col.f32.f16.f16.f32 "
        "{%0,%1,%2,%3}, {%4,%5,%6,%7}, {%8,%9}, {%0,%1,%2,%3};"
        : "+f"(d[0]), "+f"(d[1]), "+f"(d[2]), "+f"(d[3])
        : "r"(a0), "r"(a1), "r"(a2), "r"(a3), "r"(b0), "r"(b1));
}

// ---------------------------------------------------------------------------
// Kernel 1: fused QKV projection + fp16 repack (raw-view semantics).
// Unchanged from round 13/15 (14.1us measured).
// ---------------------------------------------------------------------------
__global__ __launch_bounds__(256) void proj_kernel(
    const float* __restrict__ x,
    const float* __restrict__ wq, const float* __restrict__ bq,
    const float* __restrict__ wk, const float* __restrict__ bk,
    const float* __restrict__ wv, const float* __restrict__ bv)
{
    __shared__ float xs[CTOT * 32];                 // 8KB
    __shared__ float wsq[32 * CTOT];                // 8KB
    __shared__ float wsk[32 * CTOT];                // 8KB
    __shared__ float wsv[32 * CTOT];                // 8KB
    __shared__ unsigned short vsm[32][34];          // 2.125KB

    const int b     = blockIdx.z;
    const int cbase = blockIdx.y * 32;
    const int p0    = blockIdx.x * 32;
    const int tid   = threadIdx.x;

    {
        const float4* xg = (const float4*)(x + b * (CTOT * NPOS));
        const float4* wq4 = (const float4*)(wq + cbase * CTOT);
        const float4* wk4 = (const float4*)(wk + cbase * CTOT);
        const float4* wv4 = (const float4*)(wv + cbase * CTOT);
        #pragma unroll
        for (int k = 0; k < 2; k++) {
            const int j = tid + k * 256;
            ((float4*)xs)[j]  = xg[(j >> 3) * 1024 + (p0 >> 2) + (j & 7)];
            ((float4*)wsq)[j] = wq4[j];
            ((float4*)wsk)[j] = wk4[j];
            ((float4*)wsv)[j] = wv4[j];
        }
    }
    __syncthreads();

    const int cp = tid >> 4;
    const int pg = tid & 15;
    const int l0 = 2 * cp, l1 = l0 + 1;
    const int c0 = cbase + l0, c1 = c0 + 1;

    float fq0[2], fq1[2], fk0[2], fk1[2], fv0[2], fv1[2];
    fq0[0] = fq0[1] = bq[c0];  fq1[0] = fq1[1] = bq[c1];
    fk0[0] = fk0[1] = bk[c0];  fk1[0] = fk1[1] = bk[c1];
    fv0[0] = fv0[1] = bv[c0];  fv1[0] = fv1[1] = bv[c1];

    #pragma unroll
    for (int cc = 0; cc < CTOT; cc += 4) {
        const float4 wq0 = *(const float4*)(wsq + l0 * CTOT + cc);
        const float4 wq1 = *(const float4*)(wsq + l1 * CTOT + cc);
        const float4 wk0 = *(const float4*)(wsk + l0 * CTOT + cc);
        const float4 wk1 = *(const float4*)(wsk + l1 * CTOT + cc);
        const float4 wv0 = *(const float4*)(wsv + l0 * CTOT + cc);
        const float4 wv1 = *(const float4*)(wsv + l1 * CTOT + cc);
        const float wq0a[4] = {wq0.x, wq0.y, wq0.z, wq0.w};
        const float wq1a[4] = {wq1.x, wq1.y, wq1.z, wq1.w};
        const float wk0a[4] = {wk0.x, wk0.y, wk0.z, wk0.w};
        const float wk1a[4] = {wk1.x, wk1.y, wk1.z, wk1.w};
        const float wv0a[4] = {wv0.x, wv0.y, wv0.z, wv0.w};
        const float wv1a[4] = {wv1.x, wv1.y, wv1.z, wv1.w};
        #pragma unroll
        for (int k = 0; k < 4; k++) {
            const float2 xv = *(const float2*)(xs + (cc + k) * 32 + 2 * pg);
            const float xa[2] = {xv.x, xv.y};
            #pragma unroll
            for (int i = 0; i < 2; i++) {
                fq0[i] = fmaf(wq0a[k], xa[i], fq0[i]);
                fq1[i] = fmaf(wq1a[k], xa[i], fq1[i]);
                fk0[i] = fmaf(wk0a[k], xa[i], fk0[i]);
                fk1[i] = fmaf(wk1a[k], xa[i], fk1[i]);
                fv0[i] = fmaf(wv0a[k], xa[i], fv0[i]);
                fv1[i] = fmaf(wv1a[k], xa[i], fv1[i]);
            }
        }
    }

    const int p = p0 + 2 * pg;
    *(float2*)&g_q[b * (CTOT * NPOS) + c0 * NPOS + p] = make_float2(fq0[0], fq0[1]);
    *(float2*)&g_q[b * (CTOT * NPOS) + c1 * NPOS + p] = make_float2(fq1[0], fq1[1]);

    {
        const int h   = c0 >> 3;
        const int bh  = b * 8 + h;
        const int cw0 = c0 & 7, cw1 = cw0 + 1;
        const int kb  = (p >> 3) & 511;
        const int dp  = (p >> 1) & 3;
        g_kh[(bh * NPOS + 512 * cw0 + kb) * 4 + dp] = pack_h2(fk0[1], fk0[0]);
        g_kh[(bh * NPOS + 512 * cw1 + kb) * 4 + dp] = pack_h2(fk1[1], fk1[0]);
    }

    {
        const int pl = 2 * pg;
        *(uint32_t*)&vsm[l0][pl] = pack_h2(fv0[1], fv0[0]);
        *(uint32_t*)&vsm[l1][pl] = pack_h2(fv1[1], fv1[0]);
    }
    __syncthreads();

    {
        const int lc = tid & 31;
        const int d  = tid >> 5;
        const int cg = cbase + lc;
        const int h  = cg >> 3;
        const int cw = cg & 7;
        const int ob = ((b * 8 + h) * 8 + d) * 2048 + cw * 256 + (p0 >> 4);
        #pragma unroll
        for (int kl = 0; kl < 2; kl++) {
            const uint32_t lo = vsm[lc][16 * kl + d];
            const uint32_t hi = vsm[lc][16 * kl + 8 + d];
            g_vh[ob + kl] = (hi << 16) | lo;
        }
    }
}

// ---------------------------------------------------------------------------
// Kernel 2: split-K fp16 flash attention (no-max softmax). NSPLIT=4.
// Round-15 structure with DUAL-PIPE exp: 2 of 4 f16x2 exps per u on MUFU
// (ex2.approx.f16x2), 2 on the fma/alu pipes (magic-exponent + cubic poly).
// If MUFU was the saturated pipe, demand drops ~64 -> ~40 cyc per warp-u.
// ---------------------------------------------------------------------------
struct __align__(16) KVBuf {
    uint32_t ks[1024 * 4];    // K: word = key*4 + dpair             (16384B)
    uint32_t vs[8 * 516];     // V: word = d*516 + keypair (pad 4)   (16512B)
};

__global__ __launch_bounds__(128, 6) void attn_mma_kernel(void)
{
    __shared__ KVBuf buf;     // 32.9KB -> 6 blocks/SM

    const int tid  = threadIdx.x;
    const int w    = tid >> 5;
    const int lane = tid & 31;
    const int g    = lane >> 2;
    const int c    = lane & 3;
    const int bh   = blockIdx.y;
    const int sp   = blockIdx.z;
    const int q0   = blockIdx.x * 64;
    const int base = bh * (8 * NPOS);

    // ---- stage 1024 keys of K and V with one cp.async batch
    {
        const uint32_t ks_s = smem_u32(buf.ks);
        const uint32_t vs_s = smem_u32(buf.vs);
        const uint4* kg = (const uint4*)g_kh + bh * 4096 + sp * 1024;
        const uint4* vg = (const uint4*)g_vh + bh * 4096 + sp * 128;
        #pragma unroll
        for (int i = 0; i < 8; i++) {
            const int idx = tid + i * 128;
            cp16(ks_s + (uint32_t)idx * 16u, kg + idx);
        }
        #pragma unroll
        for (int i = 0; i < 8; i++) {
            const int idx = tid + i * 128;
            const int d   = idx >> 7;
            const int col = idx & 127;
            cp16(vs_s + (uint32_t)(d * 2064 + col * 16), vg + d * 512 + col);
        }
        CP_COMMIT();
    }

    // Q fragment fp16 (scaled by log2(e)/sqrt(8)); raw-view read.
    const float SC = 0.51012921003633f;
    const int qr0 = q0 + 16 * w + g;
    const float2 ql = *(const float2*)&g_q[base + qr0 * 8 + 2 * c];
    const float2 qh = *(const float2*)&g_q[base + (qr0 + 8) * 8 + 2 * c];
    const uint32_t qa0 = pack_h2(ql.y * SC, ql.x * SC);
    const uint32_t qa1 = pack_h2(qh.y * SC, qh.x * SC);

    float o[4][4]  = {{0.f,0.f,0.f,0.f},{0.f,0.f,0.f,0.f},
                      {0.f,0.f,0.f,0.f},{0.f,0.f,0.f,0.f}};
    float la[4][4] = {{0.f,0.f,0.f,0.f},{0.f,0.f,0.f,0.f},
                      {0.f,0.f,0.f,0.f},{0.f,0.f,0.f,0.f}};
    const uint32_t ONE2 = 0x3C003C00u;   // half2(1, 1)

    CP_WAIT0();
    __syncthreads();   // the ONLY barrier in the kernel

    const uint32_t* ksb = buf.ks;
    const uint32_t* vsb = buf.vs;

    #pragma unroll 8
    for (int u = 0; u < 64; u++) {
        // keys 16u .. 16u+7 : exp on MUFU
        float s0, s1, s2, s3;
        mma_h_k8(s0, s1, s2, s3, qa0, qa1, ksb[(16 * u + g) * 4 + c]);
        const uint32_t pa0 = ex2_h2(pack_h2(s1, s0));
        const uint32_t pa1 = ex2_h2(pack_h2(s3, s2));
        // keys 16u+8 .. 16u+15 : exp on fma/alu pipes (poly)
        float t0, t1, t2, t3;
        mma_h_k8(t0, t1, t2, t3, qa0, qa1, ksb[(16 * u + 8 + g) * 4 + c]);
        const uint32_t pa2 = ex2_h2_poly(pack_h2(t1, t0));
        const uint32_t pa3 = ex2_h2_poly(pack_h2(t3, t2));

        const uint32_t vb0 = vsb[g * 516 + 8 * u + c];
        const uint32_t vb1 = vsb[g * 516 + 8 * u + c + 4];

        mma_h_k16(la[u & 3], pa0, pa1, pa2, pa3, ONE2, ONE2);
        mma_h_k16(o[u & 3],  pa0, pa1, pa2, pa3, vb0, vb1);
    }

    #pragma unroll
    for (int i = 0; i < 4; i++) {
        o[0][i]  += o[1][i]  + o[2][i]  + o[3][i];
        la[0][i] += la[1][i] + la[2][i] + la[3][i];
    }

    // partials
    const int pbase = (sp * NBH + bh) * NPOS;
    const int n0 = qr0, n1 = qr0 + 8;
    const int d0 = 2 * c;
    *(float2*)&g_po[(pbase + n0) * 8 + d0] = make_float2(o[0][0], o[0][1]);
    *(float2*)&g_po[(pbase + n1) * 8 + d0] = make_float2(o[0][2], o[0][3]);
    if (c == 0) {
        g_pl[pbase + n0] = la[0][0];
        g_pl[pbase + n1] = la[0][2];
    }
}

// ---------------------------------------------------------------------------
// Kernel 3: combine 4 split-K partials + fused epilogue (512 blocks x 128)
// ---------------------------------------------------------------------------
__global__ __launch_bounds__(128) void combine_kernel(
    const float* __restrict__ x,
    const float* __restrict__ gamma,
    float* __restrict__ out)
{
    const int i  = blockIdx.x * 128 + threadIdx.x;
    const int bh = i >> 12;
    const int n  = i & 4095;

    float od[8] = {0.f,0.f,0.f,0.f,0.f,0.f,0.f,0.f};
    float l = 0.f;
    #pragma unroll
    for (int sp = 0; sp < NSPLIT; sp++) {
        const int pbase = (sp * NBH + bh) * NPOS;
        const float4* pa = (const float4*)&g_po[(pbase + n) * 8];
        const float4 a0 = pa[0], a1 = pa[1];
        od[0] += a0.x; od[1] += a0.y; od[2] += a0.z; od[3] += a0.w;
        od[4] += a1.x; od[5] += a1.y; od[6] += a1.z; od[7] += a1.w;
        l += g_pl[pbase + n];
    }

    const float inv = 1.0f / l;
    const float gm  = gamma[0];
    const int base  = bh * (8 * NPOS);
    #pragma unroll
    for (int d = 0; d < 8; d++) {
        const int idx = base + d * NPOS + n;
        out[idx] = fmaf(gm, od[d] * inv, x[idx]);
    }
}

// ---------------------------------------------------------------------------
extern "C" void kernel_launch(void* const* d_in, const int* in_sizes, int n_in,
                              void* d_out, int out_size)
{
    const float* x     = (const float*)d_in[0];
    const float* wq    = (const float*)d_in[1];
    const float* bq    = (const float*)d_in[2];
    const float* wk    = (const float*)d_in[3];
    const float* bk    = (const float*)d_in[4];
    const float* wv    = (const float*)d_in[5];
    const float* bv    = (const float*)d_in[6];
    const float* gamma = (const float*)d_in[7];
    float* out = (float*)d_out;

    proj_kernel<<<dim3(NPOS / 32, 2, NBATCH), 256>>>(x, wq, bq, wk, bk, wv, bv);
    attn_mma_kernel<<<dim3(NPOS / 64, NBH, NSPLIT), 128>>>();
    combine_kernel<<<dim3(NBH * NPOS / 128), 128>>>(x, gamma, out);
}